// round 2
// baseline (speedup 1.0000x reference)
#include <cuda_runtime.h>

// Fused per-variable MLP, f32x2 (FFMA2) packed inner loops.
// f32x2 lanes = (even-k partial sum, odd-k partial sum), reduced at the end.
//   h0 = leaky( (w0[t] ⊙ mask_t) @ x + b0[t] )   K=128 -> 64
//   h1 = leaky( w1[t] @ h0 + b1[t] )             K=64  -> 64
//   out= w2[t] @ h1 + b2[t]                      K=64  -> 2

#define DD    128
#define HH    64
#define OO    2
#define BT    128
#define NT    256
#define SLOPE 0.01f

// Weight tile layout: [k4][i][4] with per-k4 stride of 264 floats (64*4 + 8 pad)
#define W_K4_STRIDE 264

// SMEM layout (floats)
#define OFF_X   0                          // sX  [BT][128]            16384
#define OFF_W0  (OFF_X  + BT*DD)           // sW0 [32][264]             8448
#define OFF_W1  (OFF_W0 + 32*W_K4_STRIDE)  // sW1 [16][264]             4224
#define OFF_H   (OFF_W1 + 16*W_K4_STRIDE)  // sH  [BT][64]              8192
#define OFF_H2  (OFF_H  + BT*64)           // sH2 [BT][66]              8448
#define OFF_W2  (OFF_H2 + BT*66)           // sW2 [2][64]                128
#define SMEM_FLOATS (OFF_W2 + OO*64)       // 45824 floats = 183296 B

#define FMA2(acc, a, b) \
    asm("fma.rn.f32x2 %0, %1, %2, %0;" : "+l"(acc) : "l"(a), "l"(b))

typedef unsigned long long ull;

__device__ __forceinline__ float red2(ull v) {
    float lo = __uint_as_float((unsigned)(v & 0xffffffffull));
    float hi = __uint_as_float((unsigned)(v >> 32));
    return lo + hi;
}

__global__ void __launch_bounds__(NT, 1)
fused_mlp_kernel(const float* __restrict__ x,
                 const float* __restrict__ w0,
                 const float* __restrict__ w1,
                 const float* __restrict__ w2,
                 const float* __restrict__ b0,
                 const float* __restrict__ b1,
                 const float* __restrict__ b2,
                 float* __restrict__ out)
{
    extern __shared__ float s[];
    const int t     = blockIdx.x;
    const int brow0 = blockIdx.y * BT;
    const int tid   = threadIdx.x;
    const int w     = tid >> 5;
    const int l     = tid & 31;

    // ---- stage x tile: [BT][128], coalesced float4 ----
    {
        const float4* xg  = reinterpret_cast<const float4*>(x + (size_t)brow0 * DD);
        float4*       sx4 = reinterpret_cast<float4*>(s + OFF_X);
        #pragma unroll
        for (int i = tid; i < BT * DD / 4; i += NT) sx4[i] = xg[i];
    }
    // ---- stage w0[t] into [k4][i][4], mask column j==t ----
    {
        const float4* w0g4 = reinterpret_cast<const float4*>(w0 + (size_t)t * (HH * DD));
        const int t4 = t >> 2, tc = t & 3;
        #pragma unroll
        for (int idx = tid; idx < HH * DD / 4; idx += NT) {
            int i  = idx >> 5;          // output unit 0..63
            int k4 = idx & 31;          // k-group 0..31
            float4 v = w0g4[idx];
            if (k4 == t4) {             // zero the masked input var
                if (tc == 0) v.x = 0.0f;
                else if (tc == 1) v.y = 0.0f;
                else if (tc == 2) v.z = 0.0f;
                else v.w = 0.0f;
            }
            *reinterpret_cast<float4*>(s + OFF_W0 + k4 * W_K4_STRIDE + i * 4) = v;
        }
    }
    // ---- stage w1[t] into [k4][i][4] ----
    {
        const float4* w1g4 = reinterpret_cast<const float4*>(w1 + (size_t)t * (HH * HH));
        #pragma unroll
        for (int idx = tid; idx < HH * HH / 4; idx += NT) {
            int i  = idx >> 4;          // 0..63
            int k4 = idx & 15;          // 0..15
            *reinterpret_cast<float4*>(s + OFF_W1 + k4 * W_K4_STRIDE + i * 4) = w1g4[idx];
        }
    }
    // ---- stage w2[t] ----
    if (tid < OO * HH) s[OFF_W2 + tid] = w2[(size_t)t * OO * HH + tid];
    __syncthreads();

    // =============== layer 0: [BT x 64] = sX[BT x 128] @ W0^T ===============
    {
        const int r0 = w * 16;
        ull accA[16], accB[16];
        #pragma unroll
        for (int j = 0; j < 16; j++) { accA[j] = 0ull; accB[j] = 0ull; }

        const char* swA = reinterpret_cast<const char*>(s + OFF_W0 + l * 4);
        const char* swB = reinterpret_cast<const char*>(s + OFF_W0 + (l + 32) * 4);
        const char* sx  = reinterpret_cast<const char*>(s + OFF_X + r0 * DD);

        #pragma unroll 4
        for (int k4 = 0; k4 < 32; k4++) {
            const ulonglong2 wa = *reinterpret_cast<const ulonglong2*>(swA + (size_t)k4 * (W_K4_STRIDE * 4));
            const ulonglong2 wb = *reinterpret_cast<const ulonglong2*>(swB + (size_t)k4 * (W_K4_STRIDE * 4));
            #pragma unroll
            for (int j = 0; j < 16; j++) {
                const ulonglong2 xv = *reinterpret_cast<const ulonglong2*>(sx + (size_t)j * (DD * 4) + k4 * 16);
                FMA2(accA[j], xv.x, wa.x);
                FMA2(accA[j], xv.y, wa.y);
                FMA2(accB[j], xv.x, wb.x);
                FMA2(accB[j], xv.y, wb.y);
            }
        }
        const float biaA = b0[t * HH + l];
        const float biaB = b0[t * HH + l + 32];
        float* sh = s + OFF_H + r0 * 64;
        #pragma unroll
        for (int j = 0; j < 16; j++) {
            float vA = red2(accA[j]) + biaA; vA = (vA > 0.0f) ? vA : SLOPE * vA;
            float vB = red2(accB[j]) + biaB; vB = (vB > 0.0f) ? vB : SLOPE * vB;
            sh[j * 64 + l]      = vA;
            sh[j * 64 + l + 32] = vB;
        }
    }
    __syncthreads();

    // =============== layer 1: [BT x 64] = sH[BT x 64] @ W1^T ===============
    {
        const int r0 = w * 16;
        ull accA[16], accB[16];
        #pragma unroll
        for (int j = 0; j < 16; j++) { accA[j] = 0ull; accB[j] = 0ull; }

        const char* swA = reinterpret_cast<const char*>(s + OFF_W1 + l * 4);
        const char* swB = reinterpret_cast<const char*>(s + OFF_W1 + (l + 32) * 4);
        const char* sh  = reinterpret_cast<const char*>(s + OFF_H + r0 * 64);

        #pragma unroll 4
        for (int k4 = 0; k4 < 16; k4++) {
            const ulonglong2 wa = *reinterpret_cast<const ulonglong2*>(swA + (size_t)k4 * (W_K4_STRIDE * 4));
            const ulonglong2 wb = *reinterpret_cast<const ulonglong2*>(swB + (size_t)k4 * (W_K4_STRIDE * 4));
            #pragma unroll
            for (int j = 0; j < 16; j++) {
                const ulonglong2 hv = *reinterpret_cast<const ulonglong2*>(sh + (size_t)j * (64 * 4) + k4 * 16);
                FMA2(accA[j], hv.x, wa.x);
                FMA2(accA[j], hv.y, wa.y);
                FMA2(accB[j], hv.x, wb.x);
                FMA2(accB[j], hv.y, wb.y);
            }
        }
        const float biaA = b1[t * HH + l];
        const float biaB = b1[t * HH + l + 32];
        float* sh2 = s + OFF_H2 + r0 * 66;
        #pragma unroll
        for (int j = 0; j < 16; j++) {
            float vA = red2(accA[j]) + biaA; vA = (vA > 0.0f) ? vA : SLOPE * vA;
            float vB = red2(accB[j]) + biaB; vB = (vB > 0.0f) ? vB : SLOPE * vB;
            sh2[j * 66 + l]      = vA;
            sh2[j * 66 + l + 32] = vB;
        }
    }
    __syncthreads();

    // =============== layer 2: [BT x 2], one output per thread ===============
    {
        const int row = tid >> 1;
        const int o   = tid & 1;
        const float* sh2 = s + OFF_H2 + row * 66;
        const float* sw2 = s + OFF_W2 + o * 64;
        float acc = b2[t * OO + o];
        #pragma unroll
        for (int k = 0; k < HH; k++) acc = fmaf(sh2[k], sw2[k], acc);
        out[(size_t)(brow0 + row) * (DD * OO) + t * OO + o] = acc;
    }
}

extern "C" void kernel_launch(void* const* d_in, const int* in_sizes, int n_in,
                              void* d_out, int out_size)
{
    const float* x  = (const float*)d_in[0];
    const float* w0 = (const float*)d_in[1];
    const float* w1 = (const float*)d_in[2];
    const float* w2 = (const float*)d_in[3];
    const float* b0 = (const float*)d_in[4];
    const float* b1 = (const float*)d_in[5];
    const float* b2 = (const float*)d_in[6];
    float* out = (float*)d_out;

    const int B = in_sizes[0] / DD;

    cudaFuncSetAttribute(fused_mlp_kernel,
                         cudaFuncAttributeMaxDynamicSharedMemorySize,
                         SMEM_FLOATS * (int)sizeof(float));

    dim3 grid(DD, B / BT);
    fused_mlp_kernel<<<grid, NT, SMEM_FLOATS * (int)sizeof(float)>>>(
        x, w0, w1, w2, b0, b1, b2, out);
}

// round 4
// speedup vs baseline: 2.8054x; 2.8054x over previous
#include <cuda_runtime.h>
#include <cuda_bf16.h>
#include <cstdint>

// Fused per-variable MLP on warp-level tensor cores (mma.sync m16n8k16 bf16),
// fp32 accuracy via bf16 hi/lo 3-pass split (drop lo*lo).
// One CTA = (variable t) x (128 batch rows). 8 warps:
//   warp w: unit slice m0=(w&3)*16, batch half (w>>2)*64 (8 ntiles of 8 rows).
//   D[i][r] = sum_k W[i][k] * X[r][k]   (A=W row-major, B=X^T col-major frags)

#define DD 128
#define HH 64
#define OO 2
#define BT 128
#define NT 256
#define SLOPE 0.01f

// row strides in BYTES (padded for conflict-free frag LDS)
#define XS   272   // 136 bf16 per row (K=128 + 8 pad)
#define W0S  272
#define W1S  144   // 72 bf16 per row (K=64 + 8 pad)
#define HS   144
#define H1S  264   // 66 f32 per row

// smem byte offsets
#define SM_XHI  0                        // [128][XS]   34816
#define SM_XLO  34816                    //             34816
#define SM_W0HI 69632                    // [64][272]   17408
#define SM_W0LO 87040
#define SM_W1HI 104448                   // [64][144]    9216
#define SM_W1LO 113664
#define SM_HHI  122880                   // [128][144]  18432
#define SM_HLO  141312
#define SM_H1   0                        // alias X: [128][264] f32 = 33792
#define SM_B0   159744                   // 64 f32
#define SM_B1   160000
#define SM_W2   160256                   // 128 f32
#define SMEM_BYTES 160768

static __device__ __forceinline__ void mma_bf16(float acc[4], const uint32_t a[4],
                                                uint32_t b0, uint32_t b1) {
    asm volatile(
        "mma.sync.aligned.m16n8k16.row.col.f32.bf16.bf16.f32 "
        "{%0,%1,%2,%3}, {%4,%5,%6,%7}, {%8,%9}, {%0,%1,%2,%3};"
        : "+f"(acc[0]), "+f"(acc[1]), "+f"(acc[2]), "+f"(acc[3])
        : "r"(a[0]), "r"(a[1]), "r"(a[2]), "r"(a[3]), "r"(b0), "r"(b1));
}

static __device__ __forceinline__ void split2(float a, float b, uint32_t& hi, uint32_t& lo) {
    __nv_bfloat16 ah = __float2bfloat16(a), bh = __float2bfloat16(b);
    __nv_bfloat16 al = __float2bfloat16(a - __bfloat162float(ah));
    __nv_bfloat16 bl = __float2bfloat16(b - __bfloat162float(bh));
    __nv_bfloat162 h2 = __halves2bfloat162(ah, bh), l2 = __halves2bfloat162(al, bl);
    hi = *reinterpret_cast<uint32_t*>(&h2);
    lo = *reinterpret_cast<uint32_t*>(&l2);
}
static __device__ __forceinline__ void split1(float a, __nv_bfloat16& h, __nv_bfloat16& l) {
    h = __float2bfloat16(a);
    l = __float2bfloat16(a - __bfloat162float(h));
}

__global__ void __launch_bounds__(NT, 1)
fused_mlp_hmma(const float* __restrict__ x,  const float* __restrict__ w0,
               const float* __restrict__ w1, const float* __restrict__ w2,
               const float* __restrict__ b0, const float* __restrict__ b1,
               const float* __restrict__ b2, float* __restrict__ out)
{
    extern __shared__ char smem[];
    const int t = blockIdx.x, brow0 = blockIdx.y * BT;
    const int tid = threadIdx.x, wid = tid >> 5, lid = tid & 31;
    const int gid = lid >> 2, tid4 = lid & 3;
    const int m0 = (wid & 3) * 16;        // unit slice
    const int rbB = (wid >> 2) * 64;      // batch half

    // ---------------- stage X -> hi/lo bf16 [128][136] ----------------
    {
        const float4* xg = reinterpret_cast<const float4*>(x + (size_t)brow0 * DD);
        #pragma unroll 4
        for (int idx = tid; idx < BT * DD / 4; idx += NT) {
            int r = idx >> 5, c = (idx & 31) * 4;
            float4 v = xg[idx];
            uint32_t h0, l0, h1, l1;
            split2(v.x, v.y, h0, l0); split2(v.z, v.w, h1, l1);
            int off = r * XS + c * 2;
            *reinterpret_cast<uint2*>(smem + SM_XHI + off) = make_uint2(h0, h1);
            *reinterpret_cast<uint2*>(smem + SM_XLO + off) = make_uint2(l0, l1);
        }
    }
    // ---------------- stage W0[t] masked -> hi/lo [64][136] ----------------
    {
        const float4* wg = reinterpret_cast<const float4*>(w0 + (size_t)t * HH * DD);
        const int t4 = t >> 2, te = t & 3;
        #pragma unroll 4
        for (int idx = tid; idx < HH * DD / 4; idx += NT) {
            int i = idx >> 5, c4 = idx & 31, c = c4 * 4;
            float4 v = wg[idx];
            if (c4 == t4) reinterpret_cast<float*>(&v)[te] = 0.0f;
            uint32_t h0, l0, h1, l1;
            split2(v.x, v.y, h0, l0); split2(v.z, v.w, h1, l1);
            int off = i * W0S + c * 2;
            *reinterpret_cast<uint2*>(smem + SM_W0HI + off) = make_uint2(h0, h1);
            *reinterpret_cast<uint2*>(smem + SM_W0LO + off) = make_uint2(l0, l1);
        }
    }
    // ---------------- stage W1[t] -> hi/lo [64][72] ----------------
    {
        const float4* wg = reinterpret_cast<const float4*>(w1 + (size_t)t * HH * HH);
        #pragma unroll 4
        for (int idx = tid; idx < HH * HH / 4; idx += NT) {
            int i = idx >> 4, c = (idx & 15) * 4;
            float4 v = wg[idx];
            uint32_t h0, l0, h1, l1;
            split2(v.x, v.y, h0, l0); split2(v.z, v.w, h1, l1);
            int off = i * W1S + c * 2;
            *reinterpret_cast<uint2*>(smem + SM_W1HI + off) = make_uint2(h0, h1);
            *reinterpret_cast<uint2*>(smem + SM_W1LO + off) = make_uint2(l0, l1);
        }
    }
    if (tid < HH) {
        reinterpret_cast<float*>(smem + SM_B0)[tid] = b0[t * HH + tid];
        reinterpret_cast<float*>(smem + SM_B1)[tid] = b1[t * HH + tid];
    }
    if (tid < OO * HH)
        reinterpret_cast<float*>(smem + SM_W2)[tid] = w2[(size_t)t * OO * HH + tid];
    __syncthreads();

    uint32_t wh[8][4], wl[8][4];

    // ============================ LAYER 0 ============================
    // load W0 fragments (held in regs for whole layer)
    {
        const char* WH = smem + SM_W0HI;
        const char* WL = smem + SM_W0LO;
        #pragma unroll
        for (int ks = 0; ks < 8; ks++) {
            int o00 = (m0 + gid) * W0S + ks * 32 + tid4 * 4;
            int o10 = o00 + 8 * W0S;
            wh[ks][0] = *reinterpret_cast<const uint32_t*>(WH + o00);
            wh[ks][1] = *reinterpret_cast<const uint32_t*>(WH + o10);
            wh[ks][2] = *reinterpret_cast<const uint32_t*>(WH + o00 + 16);
            wh[ks][3] = *reinterpret_cast<const uint32_t*>(WH + o10 + 16);
            wl[ks][0] = *reinterpret_cast<const uint32_t*>(WL + o00);
            wl[ks][1] = *reinterpret_cast<const uint32_t*>(WL + o10);
            wl[ks][2] = *reinterpret_cast<const uint32_t*>(WL + o00 + 16);
            wl[ks][3] = *reinterpret_cast<const uint32_t*>(WL + o10 + 16);
        }
    }
    {
        const float bA = reinterpret_cast<const float*>(smem + SM_B0)[m0 + gid];
        const float bB = reinterpret_cast<const float*>(smem + SM_B0)[m0 + gid + 8];
        #pragma unroll
        for (int nt = 0; nt < 8; nt++) {
            const int rb = rbB + nt * 8;
            const char* XH = smem + SM_XHI + (rb + gid) * XS + tid4 * 4;
            const char* XL = smem + SM_XLO + (rb + gid) * XS + tid4 * 4;
            float acc[4] = {0.f, 0.f, 0.f, 0.f};
            #pragma unroll
            for (int ks = 0; ks < 8; ks++) {
                uint32_t bh0 = *reinterpret_cast<const uint32_t*>(XH + ks * 32);
                uint32_t bh1 = *reinterpret_cast<const uint32_t*>(XH + ks * 32 + 16);
                uint32_t bl0 = *reinterpret_cast<const uint32_t*>(XL + ks * 32);
                uint32_t bl1 = *reinterpret_cast<const uint32_t*>(XL + ks * 32 + 16);
                mma_bf16(acc, wh[ks], bh0, bh1);
                mma_bf16(acc, wh[ks], bl0, bl1);
                mma_bf16(acc, wl[ks], bh0, bh1);
            }
            // epilogue -> H hi/lo [r][i]
            const int R0 = rb + 2 * tid4, I0 = m0 + gid;
            float v0 = acc[0] + bA, v1 = acc[1] + bA, v2 = acc[2] + bB, v3 = acc[3] + bB;
            v0 = (v0 > 0.f) ? v0 : SLOPE * v0;
            v1 = (v1 > 0.f) ? v1 : SLOPE * v1;
            v2 = (v2 > 0.f) ? v2 : SLOPE * v2;
            v3 = (v3 > 0.f) ? v3 : SLOPE * v3;
            __nv_bfloat16 h, l;
            char* HH_ = smem + SM_HHI; char* HL_ = smem + SM_HLO;
            split1(v0, h, l);
            *reinterpret_cast<__nv_bfloat16*>(HH_ + R0 * HS + I0 * 2) = h;
            *reinterpret_cast<__nv_bfloat16*>(HL_ + R0 * HS + I0 * 2) = l;
            split1(v1, h, l);
            *reinterpret_cast<__nv_bfloat16*>(HH_ + (R0 + 1) * HS + I0 * 2) = h;
            *reinterpret_cast<__nv_bfloat16*>(HL_ + (R0 + 1) * HS + I0 * 2) = l;
            split1(v2, h, l);
            *reinterpret_cast<__nv_bfloat16*>(HH_ + R0 * HS + (I0 + 8) * 2) = h;
            *reinterpret_cast<__nv_bfloat16*>(HL_ + R0 * HS + (I0 + 8) * 2) = l;
            split1(v3, h, l);
            *reinterpret_cast<__nv_bfloat16*>(HH_ + (R0 + 1) * HS + (I0 + 8) * 2) = h;
            *reinterpret_cast<__nv_bfloat16*>(HL_ + (R0 + 1) * HS + (I0 + 8) * 2) = l;
        }
    }
    __syncthreads();

    // ============================ LAYER 1 ============================
    {
        const char* WH = smem + SM_W1HI;
        const char* WL = smem + SM_W1LO;
        #pragma unroll
        for (int ks = 0; ks < 4; ks++) {
            int o00 = (m0 + gid) * W1S + ks * 32 + tid4 * 4;
            int o10 = o00 + 8 * W1S;
            wh[ks][0] = *reinterpret_cast<const uint32_t*>(WH + o00);
            wh[ks][1] = *reinterpret_cast<const uint32_t*>(WH + o10);
            wh[ks][2] = *reinterpret_cast<const uint32_t*>(WH + o00 + 16);
            wh[ks][3] = *reinterpret_cast<const uint32_t*>(WH + o10 + 16);
            wl[ks][0] = *reinterpret_cast<const uint32_t*>(WL + o00);
            wl[ks][1] = *reinterpret_cast<const uint32_t*>(WL + o10);
            wl[ks][2] = *reinterpret_cast<const uint32_t*>(WL + o00 + 16);
            wl[ks][3] = *reinterpret_cast<const uint32_t*>(WL + o10 + 16);
        }
        const float bA = reinterpret_cast<const float*>(smem + SM_B1)[m0 + gid];
        const float bB = reinterpret_cast<const float*>(smem + SM_B1)[m0 + gid + 8];
        #pragma unroll
        for (int nt = 0; nt < 8; nt++) {
            const int rb = rbB + nt * 8;
            const char* AH = smem + SM_HHI + (rb + gid) * HS + tid4 * 4;
            const char* AL = smem + SM_HLO + (rb + gid) * HS + tid4 * 4;
            float acc[4] = {0.f, 0.f, 0.f, 0.f};
            #pragma unroll
            for (int ks = 0; ks < 4; ks++) {
                uint32_t bh0 = *reinterpret_cast<const uint32_t*>(AH + ks * 32);
                uint32_t bh1 = *reinterpret_cast<const uint32_t*>(AH + ks * 32 + 16);
                uint32_t bl0 = *reinterpret_cast<const uint32_t*>(AL + ks * 32);
                uint32_t bl1 = *reinterpret_cast<const uint32_t*>(AL + ks * 32 + 16);
                mma_bf16(acc, wh[ks], bh0, bh1);
                mma_bf16(acc, wh[ks], bl0, bl1);
                mma_bf16(acc, wl[ks], bh0, bh1);
            }
            // epilogue -> h1 fp32 [r][i] (stride 66 f32)
            const int R0 = rb + 2 * tid4, I0 = m0 + gid;
            float v0 = acc[0] + bA, v1 = acc[1] + bA, v2 = acc[2] + bB, v3 = acc[3] + bB;
            v0 = (v0 > 0.f) ? v0 : SLOPE * v0;
            v1 = (v1 > 0.f) ? v1 : SLOPE * v1;
            v2 = (v2 > 0.f) ? v2 : SLOPE * v2;
            v3 = (v3 > 0.f) ? v3 : SLOPE * v3;
            float* H1 = reinterpret_cast<float*>(smem + SM_H1);
            H1[R0 * 66 + I0]           = v0;
            H1[(R0 + 1) * 66 + I0]     = v1;
            H1[R0 * 66 + I0 + 8]       = v2;
            H1[(R0 + 1) * 66 + I0 + 8] = v3;
        }
    }
    __syncthreads();

    // ============================ LAYER 2 (SIMT) ============================
    {
        const int row = tid >> 1, o = tid & 1;
        const float* H1 = reinterpret_cast<const float*>(smem + SM_H1) + row * 66;
        const float* W2 = reinterpret_cast<const float*>(smem + SM_W2) + o * HH;
        float acc = b2[t * OO + o];
        #pragma unroll
        for (int k = 0; k < HH; k++) acc = fmaf(H1[k], W2[k], acc);
        out[(size_t)(brow0 + row) * (DD * OO) + t * OO + o] = acc;
    }
}

extern "C" void kernel_launch(void* const* d_in, const int* in_sizes, int n_in,
                              void* d_out, int out_size)
{
    const float* x  = (const float*)d_in[0];
    const float* w0 = (const float*)d_in[1];
    const float* w1 = (const float*)d_in[2];
    const float* w2 = (const float*)d_in[3];
    const float* b0 = (const float*)d_in[4];
    const float* b1 = (const float*)d_in[5];
    const float* b2 = (const float*)d_in[6];
    float* out = (float*)d_out;

    const int B = in_sizes[0] / DD;

    cudaFuncSetAttribute(fused_mlp_hmma,
                         cudaFuncAttributeMaxDynamicSharedMemorySize, SMEM_BYTES);

    dim3 grid(DD, B / BT);
    fused_mlp_hmma<<<grid, NT, SMEM_BYTES>>>(x, w0, w1, w2, b0, b1, b2, out);
}

// round 5
// speedup vs baseline: 3.4797x; 1.2403x over previous
#include <cuda_runtime.h>
#include <cuda_bf16.h>
#include <cstdint>

// Fused per-variable MLP on mma.sync m16n8k16 bf16, hi/lo 3-pass split.
// BT=64 rows/CTA -> 105 KB smem -> 2 CTAs/SM. 3 independent accumulators.
// 8 warps: m-slice (wid&3)*16, batch half (wid>>2)*32 (4 ntiles of 8 rows).

#define DD 128
#define HH 64
#define OO 2
#define BT 64
#define NT 256
#define SLOPE 0.01f

// row strides in BYTES
#define XS   272
#define W0S  272
#define W1S  144
#define HS   144

// smem byte offsets
#define SM_XHI  0         // [64][272] 17408
#define SM_XLO  17408
#define SM_W0HI 34816     // [64][272] 17408
#define SM_W0LO 52224
#define SM_W1HI 69632     // [64][144] 9216
#define SM_W1LO 78848
#define SM_HHI  88064     // [64][144] 9216
#define SM_HLO  97280
#define SM_H1   0         // alias XHI: [64][66] f32 = 16896
#define SM_B0   106496
#define SM_B1   106752
#define SM_W2   107008    // 128 f32
#define SMEM_BYTES 107520

static __device__ __forceinline__ void mma_bf16(float acc[4], const uint32_t a[4],
                                                uint32_t b0, uint32_t b1) {
    asm volatile(
        "mma.sync.aligned.m16n8k16.row.col.f32.bf16.bf16.f32 "
        "{%0,%1,%2,%3}, {%4,%5,%6,%7}, {%8,%9}, {%0,%1,%2,%3};"
        : "+f"(acc[0]), "+f"(acc[1]), "+f"(acc[2]), "+f"(acc[3])
        : "r"(a[0]), "r"(a[1]), "r"(a[2]), "r"(a[3]), "r"(b0), "r"(b1));
}

static __device__ __forceinline__ void split2(float a, float b, uint32_t& hi, uint32_t& lo) {
    __nv_bfloat16 ah = __float2bfloat16(a), bh = __float2bfloat16(b);
    __nv_bfloat16 al = __float2bfloat16(a - __bfloat162float(ah));
    __nv_bfloat16 bl = __float2bfloat16(b - __bfloat162float(bh));
    __nv_bfloat162 h2 = __halves2bfloat162(ah, bh), l2 = __halves2bfloat162(al, bl);
    hi = *reinterpret_cast<uint32_t*>(&h2);
    lo = *reinterpret_cast<uint32_t*>(&l2);
}
static __device__ __forceinline__ void split1(float a, __nv_bfloat16& h, __nv_bfloat16& l) {
    h = __float2bfloat16(a);
    l = __float2bfloat16(a - __bfloat162float(h));
}

__global__ void __launch_bounds__(NT, 2)
fused_mlp_hmma(const float* __restrict__ x,  const float* __restrict__ w0,
               const float* __restrict__ w1, const float* __restrict__ w2,
               const float* __restrict__ b0, const float* __restrict__ b1,
               const float* __restrict__ b2, float* __restrict__ out)
{
    extern __shared__ char smem[];
    const int t = blockIdx.x, brow0 = blockIdx.y * BT;
    const int tid = threadIdx.x, wid = tid >> 5, lid = tid & 31;
    const int gid = lid >> 2, tid4 = lid & 3;
    const int m0 = (wid & 3) * 16;        // unit slice
    const int rbB = (wid >> 2) * 32;      // batch half (32 rows)

    // ---------------- stage X -> hi/lo bf16 [64][136] ----------------
    {
        const float4* xg = reinterpret_cast<const float4*>(x + (size_t)brow0 * DD);
        #pragma unroll
        for (int idx = tid; idx < BT * DD / 4; idx += NT) {
            int r = idx >> 5, c = (idx & 31) * 4;
            float4 v = xg[idx];
            uint32_t h0, l0, h1, l1;
            split2(v.x, v.y, h0, l0); split2(v.z, v.w, h1, l1);
            int off = r * XS + c * 2;
            *reinterpret_cast<uint2*>(smem + SM_XHI + off) = make_uint2(h0, h1);
            *reinterpret_cast<uint2*>(smem + SM_XLO + off) = make_uint2(l0, l1);
        }
    }
    // ---------------- stage W0[t] masked -> hi/lo ----------------
    {
        const float4* wg = reinterpret_cast<const float4*>(w0 + (size_t)t * HH * DD);
        const int t4 = t >> 2, te = t & 3;
        #pragma unroll
        for (int idx = tid; idx < HH * DD / 4; idx += NT) {
            int i = idx >> 5, c4 = idx & 31, c = c4 * 4;
            float4 v = wg[idx];
            if (c4 == t4) reinterpret_cast<float*>(&v)[te] = 0.0f;
            uint32_t h0, l0, h1, l1;
            split2(v.x, v.y, h0, l0); split2(v.z, v.w, h1, l1);
            int off = i * W0S + c * 2;
            *reinterpret_cast<uint2*>(smem + SM_W0HI + off) = make_uint2(h0, h1);
            *reinterpret_cast<uint2*>(smem + SM_W0LO + off) = make_uint2(l0, l1);
        }
    }
    // ---------------- stage W1[t] -> hi/lo ----------------
    {
        const float4* wg = reinterpret_cast<const float4*>(w1 + (size_t)t * HH * HH);
        #pragma unroll
        for (int idx = tid; idx < HH * HH / 4; idx += NT) {
            int i = idx >> 4, c = (idx & 15) * 4;
            float4 v = wg[idx];
            uint32_t h0, l0, h1, l1;
            split2(v.x, v.y, h0, l0); split2(v.z, v.w, h1, l1);
            int off = i * W1S + c * 2;
            *reinterpret_cast<uint2*>(smem + SM_W1HI + off) = make_uint2(h0, h1);
            *reinterpret_cast<uint2*>(smem + SM_W1LO + off) = make_uint2(l0, l1);
        }
    }
    if (tid < HH) {
        reinterpret_cast<float*>(smem + SM_B0)[tid] = b0[t * HH + tid];
        reinterpret_cast<float*>(smem + SM_B1)[tid] = b1[t * HH + tid];
    }
    if (tid < OO * HH)
        reinterpret_cast<float*>(smem + SM_W2)[tid] = w2[(size_t)t * OO * HH + tid];
    __syncthreads();

    uint32_t wh[8][4], wl[8][4];

    // ============================ LAYER 0 ============================
    {
        const char* WH = smem + SM_W0HI;
        const char* WL = smem + SM_W0LO;
        #pragma unroll
        for (int ks = 0; ks < 8; ks++) {
            int o00 = (m0 + gid) * W0S + ks * 32 + tid4 * 4;
            int o10 = o00 + 8 * W0S;
            wh[ks][0] = *reinterpret_cast<const uint32_t*>(WH + o00);
            wh[ks][1] = *reinterpret_cast<const uint32_t*>(WH + o10);
            wh[ks][2] = *reinterpret_cast<const uint32_t*>(WH + o00 + 16);
            wh[ks][3] = *reinterpret_cast<const uint32_t*>(WH + o10 + 16);
            wl[ks][0] = *reinterpret_cast<const uint32_t*>(WL + o00);
            wl[ks][1] = *reinterpret_cast<const uint32_t*>(WL + o10);
            wl[ks][2] = *reinterpret_cast<const uint32_t*>(WL + o00 + 16);
            wl[ks][3] = *reinterpret_cast<const uint32_t*>(WL + o10 + 16);
        }
        const float bA = reinterpret_cast<const float*>(smem + SM_B0)[m0 + gid];
        const float bB = reinterpret_cast<const float*>(smem + SM_B0)[m0 + gid + 8];
        #pragma unroll
        for (int nt = 0; nt < 4; nt++) {
            const int rb = rbB + nt * 8;
            const char* XH = smem + SM_XHI + (rb + gid) * XS + tid4 * 4;
            const char* XL = smem + SM_XLO + (rb + gid) * XS + tid4 * 4;
            float a0[4] = {0.f,0.f,0.f,0.f}, a1[4] = {0.f,0.f,0.f,0.f}, a2[4] = {0.f,0.f,0.f,0.f};
            #pragma unroll
            for (int ks = 0; ks < 8; ks++) {
                uint32_t bh0 = *reinterpret_cast<const uint32_t*>(XH + ks * 32);
                uint32_t bh1 = *reinterpret_cast<const uint32_t*>(XH + ks * 32 + 16);
                uint32_t bl0 = *reinterpret_cast<const uint32_t*>(XL + ks * 32);
                uint32_t bl1 = *reinterpret_cast<const uint32_t*>(XL + ks * 32 + 16);
                mma_bf16(a0, wh[ks], bh0, bh1);   // hi*hi
                mma_bf16(a1, wh[ks], bl0, bl1);   // hi*lo
                mma_bf16(a2, wl[ks], bh0, bh1);   // lo*hi
            }
            const int R0 = rb + 2 * tid4, I0 = m0 + gid;
            float v0 = a0[0] + a1[0] + a2[0] + bA;
            float v1 = a0[1] + a1[1] + a2[1] + bA;
            float v2 = a0[2] + a1[2] + a2[2] + bB;
            float v3 = a0[3] + a1[3] + a2[3] + bB;
            v0 = (v0 > 0.f) ? v0 : SLOPE * v0;
            v1 = (v1 > 0.f) ? v1 : SLOPE * v1;
            v2 = (v2 > 0.f) ? v2 : SLOPE * v2;
            v3 = (v3 > 0.f) ? v3 : SLOPE * v3;
            __nv_bfloat16 h, l;
            char* Hh = smem + SM_HHI; char* Hl = smem + SM_HLO;
            split1(v0, h, l);
            *reinterpret_cast<__nv_bfloat16*>(Hh + R0 * HS + I0 * 2) = h;
            *reinterpret_cast<__nv_bfloat16*>(Hl + R0 * HS + I0 * 2) = l;
            split1(v1, h, l);
            *reinterpret_cast<__nv_bfloat16*>(Hh + (R0 + 1) * HS + I0 * 2) = h;
            *reinterpret_cast<__nv_bfloat16*>(Hl + (R0 + 1) * HS + I0 * 2) = l;
            split1(v2, h, l);
            *reinterpret_cast<__nv_bfloat16*>(Hh + R0 * HS + (I0 + 8) * 2) = h;
            *reinterpret_cast<__nv_bfloat16*>(Hl + R0 * HS + (I0 + 8) * 2) = l;
            split1(v3, h, l);
            *reinterpret_cast<__nv_bfloat16*>(Hh + (R0 + 1) * HS + (I0 + 8) * 2) = h;
            *reinterpret_cast<__nv_bfloat16*>(Hl + (R0 + 1) * HS + (I0 + 8) * 2) = l;
        }
    }
    __syncthreads();

    // ============================ LAYER 1 ============================
    {
        const char* WH = smem + SM_W1HI;
        const char* WL = smem + SM_W1LO;
        #pragma unroll
        for (int ks = 0; ks < 4; ks++) {
            int o00 = (m0 + gid) * W1S + ks * 32 + tid4 * 4;
            int o10 = o00 + 8 * W1S;
            wh[ks][0] = *reinterpret_cast<const uint32_t*>(WH + o00);
            wh[ks][1] = *reinterpret_cast<const uint32_t*>(WH + o10);
            wh[ks][2] = *reinterpret_cast<const uint32_t*>(WH + o00 + 16);
            wh[ks][3] = *reinterpret_cast<const uint32_t*>(WH + o10 + 16);
            wl[ks][0] = *reinterpret_cast<const uint32_t*>(WL + o00);
            wl[ks][1] = *reinterpret_cast<const uint32_t*>(WL + o10);
            wl[ks][2] = *reinterpret_cast<const uint32_t*>(WL + o00 + 16);
            wl[ks][3] = *reinterpret_cast<const uint32_t*>(WL + o10 + 16);
        }
        const float bA = reinterpret_cast<const float*>(smem + SM_B1)[m0 + gid];
        const float bB = reinterpret_cast<const float*>(smem + SM_B1)[m0 + gid + 8];
        #pragma unroll
        for (int nt = 0; nt < 4; nt++) {
            const int rb = rbB + nt * 8;
            const char* AH = smem + SM_HHI + (rb + gid) * HS + tid4 * 4;
            const char* AL = smem + SM_HLO + (rb + gid) * HS + tid4 * 4;
            float a0[4] = {0.f,0.f,0.f,0.f}, a1[4] = {0.f,0.f,0.f,0.f}, a2[4] = {0.f,0.f,0.f,0.f};
            #pragma unroll
            for (int ks = 0; ks < 4; ks++) {
                uint32_t bh0 = *reinterpret_cast<const uint32_t*>(AH + ks * 32);
                uint32_t bh1 = *reinterpret_cast<const uint32_t*>(AH + ks * 32 + 16);
                uint32_t bl0 = *reinterpret_cast<const uint32_t*>(AL + ks * 32);
                uint32_t bl1 = *reinterpret_cast<const uint32_t*>(AL + ks * 32 + 16);
                mma_bf16(a0, wh[ks], bh0, bh1);
                mma_bf16(a1, wh[ks], bl0, bl1);
                mma_bf16(a2, wl[ks], bh0, bh1);
            }
            const int R0 = rb + 2 * tid4, I0 = m0 + gid;
            float v0 = a0[0] + a1[0] + a2[0] + bA;
            float v1 = a0[1] + a1[1] + a2[1] + bA;
            float v2 = a0[2] + a1[2] + a2[2] + bB;
            float v3 = a0[3] + a1[3] + a2[3] + bB;
            v0 = (v0 > 0.f) ? v0 : SLOPE * v0;
            v1 = (v1 > 0.f) ? v1 : SLOPE * v1;
            v2 = (v2 > 0.f) ? v2 : SLOPE * v2;
            v3 = (v3 > 0.f) ? v3 : SLOPE * v3;
            float* H1 = reinterpret_cast<float*>(smem + SM_H1);
            H1[R0 * 66 + I0]           = v0;
            H1[(R0 + 1) * 66 + I0]     = v1;
            H1[R0 * 66 + I0 + 8]       = v2;
            H1[(R0 + 1) * 66 + I0 + 8] = v3;
        }
    }
    __syncthreads();

    // ============================ LAYER 2 (SIMT) ============================
    if (tid < BT * OO) {
        const int row = tid >> 1, o = tid & 1;
        const float* H1 = reinterpret_cast<const float*>(smem + SM_H1) + row * 66;
        const float* W2 = reinterpret_cast<const float*>(smem + SM_W2) + o * HH;
        float acc = b2[t * OO + o];
        #pragma unroll
        for (int k = 0; k < HH; k++) acc = fmaf(H1[k], W2[k], acc);
        out[(size_t)(brow0 + row) * (DD * OO) + t * OO + o] = acc;
    }
}

extern "C" void kernel_launch(void* const* d_in, const int* in_sizes, int n_in,
                              void* d_out, int out_size)
{
    const float* x  = (const float*)d_in[0];
    const float* w0 = (const float*)d_in[1];
    const float* w1 = (const float*)d_in[2];
    const float* w2 = (const float*)d_in[3];
    const float* b0 = (const float*)d_in[4];
    const float* b1 = (const float*)d_in[5];
    const float* b2 = (const float*)d_in[6];
    float* out = (float*)d_out;

    const int B = in_sizes[0] / DD;

    cudaFuncSetAttribute(fused_mlp_hmma,
                         cudaFuncAttributeMaxDynamicSharedMemorySize, SMEM_BYTES);

    dim3 grid(DD, B / BT);
    fused_mlp_hmma<<<grid, NT, SMEM_BYTES>>>(x, w0, w1, w2, b0, b1, b2, out);
}

// round 6
// speedup vs baseline: 4.3697x; 1.2558x over previous
#include <cuda_runtime.h>
#include <cuda_bf16.h>
#include <cstdint>

// Fused per-variable MLP on mma.sync m16n8k16 bf16, hi/lo 3-pass split.
// R6: hi/lo splitting + masking hoisted to a prep kernel writing padded
// bf16 images in global scratch; main kernel stages via contiguous cp.async.
// BT=64 rows/CTA, 2 CTAs/SM, 3 independent accumulators.

#define DD 128
#define HH 64
#define OO 2
#define BT 64
#define NT 256
#define SLOPE 0.01f
#define BATCH 8192

// row strides in BYTES (padded, conflict-free for frag LDS: 4*gid+tid4 banks)
#define XS   272   // 136 bf16 (128 + 8 pad)
#define W0S  272
#define W1S  144   // 72 bf16 (64 + 8 pad)
#define HS   144

#define XT_BYTES  (BT*XS)      // 17408 per x-tile
#define W0T_BYTES (HH*W0S)     // 17408 per t
#define W1T_BYTES (HH*W1S)     // 9216 per t

// global scratch (pre-split bf16 images, padded to smem strides)
__device__ __align__(16) unsigned char gXhi[BATCH*XS];
__device__ __align__(16) unsigned char gXlo[BATCH*XS];
__device__ __align__(16) unsigned char gW0hi[DD*W0T_BYTES];
__device__ __align__(16) unsigned char gW0lo[DD*W0T_BYTES];
__device__ __align__(16) unsigned char gW1hi[DD*W1T_BYTES];
__device__ __align__(16) unsigned char gW1lo[DD*W1T_BYTES];

// smem byte offsets
#define SM_XHI  0         // [64][272] 17408
#define SM_XLO  17408
#define SM_W0HI 34816     // [64][272] 17408
#define SM_W0LO 52224
#define SM_W1HI 69632     // [64][144] 9216
#define SM_W1LO 78848
#define SM_HHI  88064     // [64][144] 9216
#define SM_HLO  97280
#define SM_H1   0         // alias XHI: [64][66] f32 = 16896
#define SM_B0   106496
#define SM_B1   106752
#define SM_W2   107008    // 128 f32
#define SMEM_BYTES 107520

static __device__ __forceinline__ void mma_bf16(float acc[4], const uint32_t a[4],
                                                uint32_t b0, uint32_t b1) {
    asm volatile(
        "mma.sync.aligned.m16n8k16.row.col.f32.bf16.bf16.f32 "
        "{%0,%1,%2,%3}, {%4,%5,%6,%7}, {%8,%9}, {%0,%1,%2,%3};"
        : "+f"(acc[0]), "+f"(acc[1]), "+f"(acc[2]), "+f"(acc[3])
        : "r"(a[0]), "r"(a[1]), "r"(a[2]), "r"(a[3]), "r"(b0), "r"(b1));
}
static __device__ __forceinline__ void split2(float a, float b, uint32_t& hi, uint32_t& lo) {
    __nv_bfloat16 ah = __float2bfloat16(a), bh = __float2bfloat16(b);
    __nv_bfloat16 al = __float2bfloat16(a - __bfloat162float(ah));
    __nv_bfloat16 bl = __float2bfloat16(b - __bfloat162float(bh));
    __nv_bfloat162 h2 = __halves2bfloat162(ah, bh), l2 = __halves2bfloat162(al, bl);
    hi = *reinterpret_cast<uint32_t*>(&h2);
    lo = *reinterpret_cast<uint32_t*>(&l2);
}
static __device__ __forceinline__ void split1(float a, __nv_bfloat16& h, __nv_bfloat16& l) {
    h = __float2bfloat16(a);
    l = __float2bfloat16(a - __bfloat162float(h));
}
#define CP16(sdst, gsrc) asm volatile( \
    "cp.async.cg.shared.global [%0], [%1], 16;" :: "r"(sdst), "l"(gsrc))

// ===================== prep: split/mask/pad X, W0, W1 =====================
#define NX4  (BATCH*DD/4)        // 262144
#define NW04 (DD*HH*DD/4)        // 262144
#define NW14 (DD*HH*HH/4)        // 131072

__global__ void __launch_bounds__(256)
prep_kernel(const float* __restrict__ x, const float* __restrict__ w0,
            const float* __restrict__ w1)
{
    int idx = blockIdx.x * 256 + threadIdx.x;
    if (idx < NX4) {
        int r = idx >> 5, c = idx & 31;
        float4 v = reinterpret_cast<const float4*>(x)[idx];
        uint32_t h0, l0, h1, l1;
        split2(v.x, v.y, h0, l0); split2(v.z, v.w, h1, l1);
        *reinterpret_cast<uint2*>(gXhi + r * XS + c * 8) = make_uint2(h0, h1);
        *reinterpret_cast<uint2*>(gXlo + r * XS + c * 8) = make_uint2(l0, l1);
    } else if (idx < NX4 + NW04) {
        int j = idx - NX4;
        int t = j >> 11, k = j & 2047;       // 2048 float4 per t
        int i = k >> 5, c4 = k & 31;
        float4 v = reinterpret_cast<const float4*>(w0)[j];
        if (c4 == (t >> 2)) reinterpret_cast<float*>(&v)[t & 3] = 0.0f;
        uint32_t h0, l0, h1, l1;
        split2(v.x, v.y, h0, l0); split2(v.z, v.w, h1, l1);
        *reinterpret_cast<uint2*>(gW0hi + t * W0T_BYTES + i * W0S + c4 * 8) = make_uint2(h0, h1);
        *reinterpret_cast<uint2*>(gW0lo + t * W0T_BYTES + i * W0S + c4 * 8) = make_uint2(l0, l1);
    } else if (idx < NX4 + NW04 + NW14) {
        int j = idx - NX4 - NW04;
        int t = j >> 10, k = j & 1023;       // 1024 float4 per t
        int i = k >> 4, c4 = k & 15;
        float4 v = reinterpret_cast<const float4*>(w1)[j];
        uint32_t h0, l0, h1, l1;
        split2(v.x, v.y, h0, l0); split2(v.z, v.w, h1, l1);
        *reinterpret_cast<uint2*>(gW1hi + t * W1T_BYTES + i * W1S + c4 * 8) = make_uint2(h0, h1);
        *reinterpret_cast<uint2*>(gW1lo + t * W1T_BYTES + i * W1S + c4 * 8) = make_uint2(l0, l1);
    }
}

// ============================ main kernel ============================
__global__ void __launch_bounds__(NT, 2)
fused_mlp_hmma(const float* __restrict__ w2, const float* __restrict__ b0,
               const float* __restrict__ b1, const float* __restrict__ b2,
               float* __restrict__ out)
{
    extern __shared__ char smem[];
    const int t = blockIdx.x, brow0 = blockIdx.y * BT;
    const int tid = threadIdx.x, wid = tid >> 5, lid = tid & 31;
    const int gid = lid >> 2, tid4 = lid & 3;
    const int m0 = (wid & 3) * 16;
    const int rbB = (wid >> 2) * 32;

    // ---- staging: pure contiguous 16B cp.async block copies ----
    {
        uint32_t sb;
        asm("{ .reg .u64 tt; cvta.to.shared.u64 tt, %1; cvt.u32.u64 %0, tt; }"
            : "=r"(sb) : "l"(smem));
        const unsigned char* xh = gXhi + (size_t)brow0 * XS;
        const unsigned char* xl = gXlo + (size_t)brow0 * XS;
        const unsigned char* w0h = gW0hi + (size_t)t * W0T_BYTES;
        const unsigned char* w0l = gW0lo + (size_t)t * W0T_BYTES;
        const unsigned char* w1h = gW1hi + (size_t)t * W1T_BYTES;
        const unsigned char* w1l = gW1lo + (size_t)t * W1T_BYTES;
        #pragma unroll
        for (int i = tid; i < XT_BYTES / 16; i += NT) {
            CP16(sb + SM_XHI + i * 16, xh + i * 16);
            CP16(sb + SM_XLO + i * 16, xl + i * 16);
            CP16(sb + SM_W0HI + i * 16, w0h + i * 16);
            CP16(sb + SM_W0LO + i * 16, w0l + i * 16);
        }
        #pragma unroll
        for (int i = tid; i < W1T_BYTES / 16; i += NT) {
            CP16(sb + SM_W1HI + i * 16, w1h + i * 16);
            CP16(sb + SM_W1LO + i * 16, w1l + i * 16);
        }
        asm volatile("cp.async.commit_group;" ::: "memory");
    }
    if (tid < HH) {
        reinterpret_cast<float*>(smem + SM_B0)[tid] = b0[t * HH + tid];
        reinterpret_cast<float*>(smem + SM_B1)[tid] = b1[t * HH + tid];
    }
    if (tid < OO * HH)
        reinterpret_cast<float*>(smem + SM_W2)[tid] = w2[(size_t)t * OO * HH + tid];
    asm volatile("cp.async.wait_group 0;" ::: "memory");
    __syncthreads();

    uint32_t wh[8][4], wl[8][4];

    // ============================ LAYER 0 ============================
    {
        const char* WH = smem + SM_W0HI;
        const char* WL = smem + SM_W0LO;
        #pragma unroll
        for (int ks = 0; ks < 8; ks++) {
            int o00 = (m0 + gid) * W0S + ks * 32 + tid4 * 4;
            int o10 = o00 + 8 * W0S;
            wh[ks][0] = *reinterpret_cast<const uint32_t*>(WH + o00);
            wh[ks][1] = *reinterpret_cast<const uint32_t*>(WH + o10);
            wh[ks][2] = *reinterpret_cast<const uint32_t*>(WH + o00 + 16);
            wh[ks][3] = *reinterpret_cast<const uint32_t*>(WH + o10 + 16);
            wl[ks][0] = *reinterpret_cast<const uint32_t*>(WL + o00);
            wl[ks][1] = *reinterpret_cast<const uint32_t*>(WL + o10);
            wl[ks][2] = *reinterpret_cast<const uint32_t*>(WL + o00 + 16);
            wl[ks][3] = *reinterpret_cast<const uint32_t*>(WL + o10 + 16);
        }
        const float bA = reinterpret_cast<const float*>(smem + SM_B0)[m0 + gid];
        const float bB = reinterpret_cast<const float*>(smem + SM_B0)[m0 + gid + 8];
        #pragma unroll
        for (int nt = 0; nt < 4; nt++) {
            const int rb = rbB + nt * 8;
            const char* XH = smem + SM_XHI + (rb + gid) * XS + tid4 * 4;
            const char* XL = smem + SM_XLO + (rb + gid) * XS + tid4 * 4;
            float a0[4] = {0.f,0.f,0.f,0.f}, a1[4] = {0.f,0.f,0.f,0.f}, a2[4] = {0.f,0.f,0.f,0.f};
            #pragma unroll
            for (int ks = 0; ks < 8; ks++) {
                uint32_t bh0 = *reinterpret_cast<const uint32_t*>(XH + ks * 32);
                uint32_t bh1 = *reinterpret_cast<const uint32_t*>(XH + ks * 32 + 16);
                uint32_t bl0 = *reinterpret_cast<const uint32_t*>(XL + ks * 32);
                uint32_t bl1 = *reinterpret_cast<const uint32_t*>(XL + ks * 32 + 16);
                mma_bf16(a0, wh[ks], bh0, bh1);
                mma_bf16(a1, wh[ks], bl0, bl1);
                mma_bf16(a2, wl[ks], bh0, bh1);
            }
            const int R0 = rb + 2 * tid4, I0 = m0 + gid;
            float v0 = a0[0] + a1[0] + a2[0] + bA;
            float v1 = a0[1] + a1[1] + a2[1] + bA;
            float v2 = a0[2] + a1[2] + a2[2] + bB;
            float v3 = a0[3] + a1[3] + a2[3] + bB;
            v0 = (v0 > 0.f) ? v0 : SLOPE * v0;
            v1 = (v1 > 0.f) ? v1 : SLOPE * v1;
            v2 = (v2 > 0.f) ? v2 : SLOPE * v2;
            v3 = (v3 > 0.f) ? v3 : SLOPE * v3;
            __nv_bfloat16 h, l;
            char* Hh = smem + SM_HHI; char* Hl = smem + SM_HLO;
            split1(v0, h, l);
            *reinterpret_cast<__nv_bfloat16*>(Hh + R0 * HS + I0 * 2) = h;
            *reinterpret_cast<__nv_bfloat16*>(Hl + R0 * HS + I0 * 2) = l;
            split1(v1, h, l);
            *reinterpret_cast<__nv_bfloat16*>(Hh + (R0 + 1) * HS + I0 * 2) = h;
            *reinterpret_cast<__nv_bfloat16*>(Hl + (R0 + 1) * HS + I0 * 2) = l;
            split1(v2, h, l);
            *reinterpret_cast<__nv_bfloat16*>(Hh + R0 * HS + (I0 + 8) * 2) = h;
            *reinterpret_cast<__nv_bfloat16*>(Hl + R0 * HS + (I0 + 8) * 2) = l;
            split1(v3, h, l);
            *reinterpret_cast<__nv_bfloat16*>(Hh + (R0 + 1) * HS + (I0 + 8) * 2) = h;
            *reinterpret_cast<__nv_bfloat16*>(Hl + (R0 + 1) * HS + (I0 + 8) * 2) = l;
        }
    }
    __syncthreads();

    // ============================ LAYER 1 ============================
    {
        const char* WH = smem + SM_W1HI;
        const char* WL = smem + SM_W1LO;
        #pragma unroll
        for (int ks = 0; ks < 4; ks++) {
            int o00 = (m0 + gid) * W1S + ks * 32 + tid4 * 4;
            int o10 = o00 + 8 * W1S;
            wh[ks][0] = *reinterpret_cast<const uint32_t*>(WH + o00);
            wh[ks][1] = *reinterpret_cast<const uint32_t*>(WH + o10);
            wh[ks][2] = *reinterpret_cast<const uint32_t*>(WH + o00 + 16);
            wh[ks][3] = *reinterpret_cast<const uint32_t*>(WH + o10 + 16);
            wl[ks][0] = *reinterpret_cast<const uint32_t*>(WL + o00);
            wl[ks][1] = *reinterpret_cast<const uint32_t*>(WL + o10);
            wl[ks][2] = *reinterpret_cast<const uint32_t*>(WL + o00 + 16);
            wl[ks][3] = *reinterpret_cast<const uint32_t*>(WL + o10 + 16);
        }
        const float bA = reinterpret_cast<const float*>(smem + SM_B1)[m0 + gid];
        const float bB = reinterpret_cast<const float*>(smem + SM_B1)[m0 + gid + 8];
        #pragma unroll
        for (int nt = 0; nt < 4; nt++) {
            const int rb = rbB + nt * 8;
            const char* AH = smem + SM_HHI + (rb + gid) * HS + tid4 * 4;
            const char* AL = smem + SM_HLO + (rb + gid) * HS + tid4 * 4;
            float a0[4] = {0.f,0.f,0.f,0.f}, a1[4] = {0.f,0.f,0.f,0.f}, a2[4] = {0.f,0.f,0.f,0.f};
            #pragma unroll
            for (int ks = 0; ks < 4; ks++) {
                uint32_t bh0 = *reinterpret_cast<const uint32_t*>(AH + ks * 32);
                uint32_t bh1 = *reinterpret_cast<const uint32_t*>(AH + ks * 32 + 16);
                uint32_t bl0 = *reinterpret_cast<const uint32_t*>(AL + ks * 32);
                uint32_t bl1 = *reinterpret_cast<const uint32_t*>(AL + ks * 32 + 16);
                mma_bf16(a0, wh[ks], bh0, bh1);
                mma_bf16(a1, wh[ks], bl0, bl1);
                mma_bf16(a2, wl[ks], bh0, bh1);
            }
            const int R0 = rb + 2 * tid4, I0 = m0 + gid;
            float v0 = a0[0] + a1[0] + a2[0] + bA;
            float v1 = a0[1] + a1[1] + a2[1] + bA;
            float v2 = a0[2] + a1[2] + a2[2] + bB;
            float v3 = a0[3] + a1[3] + a2[3] + bB;
            v0 = (v0 > 0.f) ? v0 : SLOPE * v0;
            v1 = (v1 > 0.f) ? v1 : SLOPE * v1;
            v2 = (v2 > 0.f) ? v2 : SLOPE * v2;
            v3 = (v3 > 0.f) ? v3 : SLOPE * v3;
            float* H1 = reinterpret_cast<float*>(smem + SM_H1);
            H1[R0 * 66 + I0]           = v0;
            H1[(R0 + 1) * 66 + I0]     = v1;
            H1[R0 * 66 + I0 + 8]       = v2;
            H1[(R0 + 1) * 66 + I0 + 8] = v3;
        }
    }
    __syncthreads();

    // ============================ LAYER 2 (SIMT) ============================
    if (tid < BT * OO) {
        const int row = tid >> 1, o = tid & 1;
        const float* H1 = reinterpret_cast<const float*>(smem + SM_H1) + row * 66;
        const float* W2 = reinterpret_cast<const float*>(smem + SM_W2) + o * HH;
        float acc = b2[t * OO + o];
        #pragma unroll
        for (int k = 0; k < HH; k++) acc = fmaf(H1[k], W2[k], acc);
        out[(size_t)(brow0 + row) * (DD * OO) + t * OO + o] = acc;
    }
}

extern "C" void kernel_launch(void* const* d_in, const int* in_sizes, int n_in,
                              void* d_out, int out_size)
{
    const float* x  = (const float*)d_in[0];
    const float* w0 = (const float*)d_in[1];
    const float* w1 = (const float*)d_in[2];
    const float* w2 = (const float*)d_in[3];
    const float* b0 = (const float*)d_in[4];
    const float* b1 = (const float*)d_in[5];
    const float* b2 = (const float*)d_in[6];
    float* out = (float*)d_out;

    const int B = in_sizes[0] / DD;

    cudaFuncSetAttribute(fused_mlp_hmma,
                         cudaFuncAttributeMaxDynamicSharedMemorySize, SMEM_BYTES);

    const int total4 = NX4 + NW04 + NW14;          // 655360
    prep_kernel<<<(total4 + 255) / 256, 256>>>(x, w0, w1);

    dim3 grid(DD, B / BT);
    fused_mlp_hmma<<<grid, NT, SMEM_BYTES>>>(w2, b0, b1, b2, out);
}